// round 1
// baseline (speedup 1.0000x reference)
#include <cuda_runtime.h>
#include <math.h>

#define D 128
#define N_HALF 4096
#define NS 8192          // total samples
#define NTILE 64         // 8192 / 128
#define NBLOCKS 2080     // 64*65/2 lower-triangular tiles

// ---------------- device scratch (no allocations allowed) ----------------
__device__ float  g_sq[NS];       // per-row squared norms
__device__ float  g_colsum[D];    // per-column sums over all 8192 rows
__device__ float  g_sumsq;        // sum of g_sq
__device__ float  g_c;            // log2(e) / (16*bw)
__device__ double g_total;        // signed weighted kernel sum (off-diagonal)

// ---------------- helpers ----------------
__device__ __forceinline__ float ex2f(float x) {
    float y; asm("ex2.approx.ftz.f32 %0, %1;" : "=f"(y) : "f"(x)); return y;
}
__device__ __forceinline__ unsigned long long pk2(float lo, float hi) {
    unsigned long long r;
    asm("mov.b64 %0, {%1, %2};" : "=l"(r) : "f"(lo), "f"(hi));
    return r;
}
__device__ __forceinline__ void upk2(unsigned long long v, float& lo, float& hi) {
    asm("mov.b64 {%0, %1}, %2;" : "=f"(lo), "=f"(hi) : "l"(v));
}
__device__ __forceinline__ unsigned long long fma2(unsigned long long a,
                                                   unsigned long long b,
                                                   unsigned long long c) {
    unsigned long long d;
    asm("fma.rn.f32x2 %0, %1, %2, %3;" : "=l"(d) : "l"(a), "l"(b), "l"(c));
    return d;
}

// ---------------- kernel 0: zero accumulators (graph replays!) ----------------
__global__ void k_init() {
    int t = threadIdx.x;
    if (t < D)       g_colsum[t] = 0.0f;
    if (t == D)      g_sumsq = 0.0f;
    if (t == D + 1)  g_total = 0.0;
}

// ---------------- kernel 1: row norms + column sums ----------------
// grid 64, block 256 (8 warps). Block handles 128 rows; warp w handles 16 rows.
__global__ void k_rowstats(const float* __restrict__ src, const float* __restrict__ tgt) {
    int w = threadIdx.x >> 5, lane = threadIdx.x & 31;
    float cs0 = 0.f, cs1 = 0.f, cs2 = 0.f, cs3 = 0.f, wsq = 0.f;
    for (int it = 0; it < 16; ++it) {
        int i = blockIdx.x * 128 + w * 16 + it;
        const float* row = (i < N_HALF) ? src + (size_t)i * D
                                        : tgt + (size_t)(i - N_HALF) * D;
        float4 v = *(const float4*)(row + lane * 4);
        cs0 += v.x; cs1 += v.y; cs2 += v.z; cs3 += v.w;
        float s = v.x * v.x + v.y * v.y + v.z * v.z + v.w * v.w;
        #pragma unroll
        for (int o = 16; o; o >>= 1) s += __shfl_xor_sync(0xffffffffu, s, o);
        if (lane == 0) { g_sq[i] = s; wsq += s; }
    }
    atomicAdd(&g_colsum[lane * 4 + 0], cs0);
    atomicAdd(&g_colsum[lane * 4 + 1], cs1);
    atomicAdd(&g_colsum[lane * 4 + 2], cs2);
    atomicAdd(&g_colsum[lane * 4 + 3], cs3);
    if (lane == 0) atomicAdd(&g_sumsq, wsq);
}

// ---------------- kernel 2: bandwidth ----------------
// sum(L2) = 2*NS*sum(sq) - 2*||colsum||^2 ; bw = sumL2/(NS^2-NS)/4 ; c = log2e/(16*bw)
__global__ void k_bw() {
    __shared__ double sh[D];
    int t = threadIdx.x;
    double m = (double)g_colsum[t];
    sh[t] = m * m;
    __syncthreads();
    for (int o = 64; o; o >>= 1) {
        if (t < o) sh[t] += sh[t + o];
        __syncthreads();
    }
    if (t == 0) {
        double sumL2 = 2.0 * (double)NS * (double)g_sumsq - 2.0 * sh[0];
        double bw = sumL2 / ((double)NS * (double)NS - (double)NS) / 4.0;
        g_c = (float)(1.4426950408889634 / (bw * 16.0));
    }
}

// ---------------- kernel 3: fused Gram tile + RBF-sum epilogue ----------------
// One block = one 128x128 tile of the 8192x8192 interaction matrix,
// lower triangle only (bi >= bj). 256 threads, 8x8 micro-tiles via packed f32x2 FMA.
__global__ void __launch_bounds__(256) k_main(const float* __restrict__ src,
                                              const float* __restrict__ tgt) {
    __shared__ float sA[16 * 132];
    __shared__ float sB[16 * 132];

    int idx = blockIdx.x;
    int bi = (int)((sqrtf(8.0f * (float)idx + 1.0f) - 1.0f) * 0.5f);
    while ((bi + 1) * (bi + 2) / 2 <= idx) bi++;
    while (bi * (bi + 1) / 2 > idx) bi--;
    int bj = idx - bi * (bi + 1) / 2;

    const float* Ab = (bi < 32) ? src + (size_t)bi * 128 * D
                                : tgt + (size_t)(bi - 32) * 128 * D;
    const float* Bb = (bj < 32) ? src + (size_t)bj * 128 * D
                                : tgt + (size_t)(bj - 32) * 128 * D;

    int tid = threadIdx.x;
    int tx = tid & 15;        // column group: cols tx*8 .. tx*8+7
    int ty = tid >> 4;        // row group:    rows ty*8 .. ty*8+7

    unsigned long long acc[8][4];
    #pragma unroll
    for (int i = 0; i < 8; ++i)
        #pragma unroll
        for (int j = 0; j < 4; ++j) acc[i][j] = 0ull;

    int r0 = tid >> 2;            // rows 0..63
    int r1 = r0 + 64;             // rows 64..127
    int q  = tid & 3;             // which 4-float chunk of the 16-wide k slab

    for (int kc = 0; kc < 8; ++kc) {
        __syncthreads();
        {
            float4 va = *(const float4*)(Ab + (size_t)r0 * D + kc * 16 + q * 4);
            sA[(q * 4 + 0) * 132 + r0] = va.x;
            sA[(q * 4 + 1) * 132 + r0] = va.y;
            sA[(q * 4 + 2) * 132 + r0] = va.z;
            sA[(q * 4 + 3) * 132 + r0] = va.w;
            float4 vb = *(const float4*)(Bb + (size_t)r0 * D + kc * 16 + q * 4);
            sB[(q * 4 + 0) * 132 + r0] = vb.x;
            sB[(q * 4 + 1) * 132 + r0] = vb.y;
            sB[(q * 4 + 2) * 132 + r0] = vb.z;
            sB[(q * 4 + 3) * 132 + r0] = vb.w;
            va = *(const float4*)(Ab + (size_t)r1 * D + kc * 16 + q * 4);
            sA[(q * 4 + 0) * 132 + r1] = va.x;
            sA[(q * 4 + 1) * 132 + r1] = va.y;
            sA[(q * 4 + 2) * 132 + r1] = va.z;
            sA[(q * 4 + 3) * 132 + r1] = va.w;
            vb = *(const float4*)(Bb + (size_t)r1 * D + kc * 16 + q * 4);
            sB[(q * 4 + 0) * 132 + r1] = vb.x;
            sB[(q * 4 + 1) * 132 + r1] = vb.y;
            sB[(q * 4 + 2) * 132 + r1] = vb.z;
            sB[(q * 4 + 3) * 132 + r1] = vb.w;
        }
        __syncthreads();

        #pragma unroll
        for (int kk = 0; kk < 16; ++kk) {
            float4 a0 = *(const float4*)&sA[kk * 132 + ty * 8];
            float4 a1 = *(const float4*)&sA[kk * 132 + ty * 8 + 4];
            float4 b0 = *(const float4*)&sB[kk * 132 + tx * 8];
            float4 b1 = *(const float4*)&sB[kk * 132 + tx * 8 + 4];
            unsigned long long bp[4] = { pk2(b0.x, b0.y), pk2(b0.z, b0.w),
                                         pk2(b1.x, b1.y), pk2(b1.z, b1.w) };
            float av[8] = { a0.x, a0.y, a0.z, a0.w, a1.x, a1.y, a1.z, a1.w };
            #pragma unroll
            for (int mi = 0; mi < 8; ++mi) {
                unsigned long long ap = pk2(av[mi], av[mi]);
                #pragma unroll
                for (int nj = 0; nj < 4; ++nj)
                    acc[mi][nj] = fma2(ap, bp[nj], acc[mi][nj]);
            }
        }
    }

    // ---- epilogue: L2 -> t = 2^(-L2*c) -> t + t^2 + t^4 + t^8 + t^16 ----
    float c = g_c;
    float sqi[8], sqj[8];
    #pragma unroll
    for (int e = 0; e < 8; ++e) {
        sqi[e] = g_sq[bi * 128 + ty * 8 + e];
        sqj[e] = g_sq[bj * 128 + tx * 8 + e];
    }
    bool dt = (bi == bj);
    float p = 0.f;
    #pragma unroll
    for (int mi = 0; mi < 8; ++mi) {
        #pragma unroll
        for (int nj = 0; nj < 4; ++nj) {
            float d0, d1;
            upk2(acc[mi][nj], d0, d1);
            int col0 = nj * 2, col1 = nj * 2 + 1;
            {
                float L2 = fmaxf(sqi[mi] + sqj[col0] - 2.0f * d0, 0.0f);
                float t  = ex2f(-L2 * c);
                float t2 = t * t, t4 = t2 * t2, t8 = t4 * t4, t16 = t8 * t8;
                float ks = t + t2 + t4 + t8 + t16;
                if (!dt || (ty * 8 + mi) > (tx * 8 + col0)) p += ks;
            }
            {
                float L2 = fmaxf(sqi[mi] + sqj[col1] - 2.0f * d1, 0.0f);
                float t  = ex2f(-L2 * c);
                float t2 = t * t, t4 = t2 * t2, t8 = t4 * t4, t16 = t8 * t8;
                float ks = t + t2 + t4 + t8 + t16;
                if (!dt || (ty * 8 + mi) > (tx * 8 + col1)) p += ks;
            }
        }
    }
    // off-diagonal tiles counted twice by symmetry; sign constant per tile
    float scale = ((bi < 32) == (bj < 32)) ? 2.0f : -2.0f;
    p *= scale;

    __syncthreads();
    float* red = sA;
    red[tid] = p;
    __syncthreads();
    for (int o = 128; o; o >>= 1) {
        if (tid < o) red[tid] += red[tid + o];
        __syncthreads();
    }
    if (tid == 0) atomicAdd(&g_total, (double)red[0]);
}

// ---------------- kernel 4: finalize ----------------
// diagonal contributes K(i,i)=5 for all 2n rows: 5*8192 = 40960
__global__ void k_final(float* out) {
    out[0] = (float)((g_total + 40960.0) / 16777216.0);  // / n^2, n=4096
}

// ---------------- launcher ----------------
extern "C" void kernel_launch(void* const* d_in, const int* in_sizes, int n_in,
                              void* d_out, int out_size) {
    const float* src = (const float*)d_in[0];
    const float* tgt = (const float*)d_in[1];
    float* out = (float*)d_out;
    (void)in_sizes; (void)n_in; (void)out_size;

    k_init<<<1, 256>>>();
    k_rowstats<<<64, 256>>>(src, tgt);
    k_bw<<<1, D>>>();
    k_main<<<NBLOCKS, 256>>>(src, tgt);
    k_final<<<1, 1>>>(out);
}

// round 3
// speedup vs baseline: 1.8580x; 1.8580x over previous
#include <cuda_runtime.h>
#include <cuda_bf16.h>
#include <math.h>
#include <stdint.h>

#define D 128
#define N_HALF 4096
#define NS 8192
#define NBLOCKS 2080     // 64*65/2 lower-triangular 128x128 tiles

// ---------------- device scratch ----------------
__device__ float  g_sq[NS];
__device__ float  g_colsum[D];
__device__ float  g_sumsq;
__device__ float  g_c;
__device__ double g_total;
__device__ __align__(16) __nv_bfloat16 g_hi[NS * D];
__device__ __align__(16) __nv_bfloat16 g_lo[NS * D];

// ---------------- helpers ----------------
__device__ __forceinline__ float ex2f(float x) {
    float y; asm("ex2.approx.ftz.f32 %0, %1;" : "=f"(y) : "f"(x)); return y;
}
__device__ __forceinline__ uint32_t smem_u32(const void* p) {
    uint32_t a;
    asm("{ .reg .u64 t; cvta.to.shared.u64 t, %1; cvt.u32.u64 %0, t; }" : "=r"(a) : "l"(p));
    return a;
}
__device__ __forceinline__ void ldsm4(uint32_t* r, uint32_t addr) {
    asm volatile("ldmatrix.sync.aligned.m8n8.x4.shared.b16 {%0,%1,%2,%3}, [%4];"
        : "=r"(r[0]), "=r"(r[1]), "=r"(r[2]), "=r"(r[3]) : "r"(addr));
}
__device__ __forceinline__ void mma16816(float* d, const uint32_t* a, const uint32_t* b) {
    asm volatile("mma.sync.aligned.m16n8k16.row.col.f32.bf16.bf16.f32 "
        "{%0,%1,%2,%3}, {%4,%5,%6,%7}, {%8,%9}, {%0,%1,%2,%3};"
        : "+f"(d[0]), "+f"(d[1]), "+f"(d[2]), "+f"(d[3])
        : "r"(a[0]), "r"(a[1]), "r"(a[2]), "r"(a[3]), "r"(b[0]), "r"(b[1]));
}
#define CP_ASYNC16(sm, gp) \
    asm volatile("cp.async.cg.shared.global [%0], [%1], 16;" :: "r"(sm), "l"(gp) : "memory")
#define CP_COMMIT() asm volatile("cp.async.commit_group;" ::: "memory")
#define CP_WAIT0()  asm volatile("cp.async.wait_group 0;" ::: "memory")

// ---- smem layout: k-chunk buffers, 128 rows x 32 bf16 (64B) padded to 80B/row ----
#define SROW   80
#define MATSZ  (128 * SROW)          // 10240 B per matrix chunk
#define BUFSZ  (4 * MATSZ)           // Ahi, Alo, Bhi, Blo
#define SQI_OFF (2 * BUFSZ)          // 81920
#define SQJ_OFF (SQI_OFF + 512)
#define RED_OFF (SQJ_OFF + 512)
#define SMEM_BYTES (RED_OFF + 1024)  // 83968

// ---------------- kernel 0: zero accumulators ----------------
__global__ void k_init() {
    int t = threadIdx.x;
    if (t < D)       g_colsum[t] = 0.0f;
    if (t == D)      g_sumsq = 0.0f;
    if (t == D + 1)  g_total = 0.0;
}

// ---------------- kernel 1: row norms + column sums + bf16 hi/lo split ----------------
__global__ void k_rowstats(const float* __restrict__ src, const float* __restrict__ tgt) {
    int w = threadIdx.x >> 5, lane = threadIdx.x & 31;
    float cs0 = 0.f, cs1 = 0.f, cs2 = 0.f, cs3 = 0.f, wsq = 0.f;
    for (int it = 0; it < 16; ++it) {
        int i = blockIdx.x * 128 + w * 16 + it;
        const float* row = (i < N_HALF) ? src + (size_t)i * D
                                        : tgt + (size_t)(i - N_HALF) * D;
        float4 v = *(const float4*)(row + lane * 4);
        cs0 += v.x; cs1 += v.y; cs2 += v.z; cs3 += v.w;

        __nv_bfloat16 h0 = __float2bfloat16(v.x);
        __nv_bfloat16 h1 = __float2bfloat16(v.y);
        __nv_bfloat16 h2 = __float2bfloat16(v.z);
        __nv_bfloat16 h3 = __float2bfloat16(v.w);
        __nv_bfloat16 l0 = __float2bfloat16(v.x - __bfloat162float(h0));
        __nv_bfloat16 l1 = __float2bfloat16(v.y - __bfloat162float(h1));
        __nv_bfloat16 l2 = __float2bfloat16(v.z - __bfloat162float(h2));
        __nv_bfloat16 l3 = __float2bfloat16(v.w - __bfloat162float(h3));
        size_t base = (size_t)i * D + lane * 4;
        ((__nv_bfloat162*)g_hi)[base / 2]     = __nv_bfloat162(h0, h1);
        ((__nv_bfloat162*)g_hi)[base / 2 + 1] = __nv_bfloat162(h2, h3);
        ((__nv_bfloat162*)g_lo)[base / 2]     = __nv_bfloat162(l0, l1);
        ((__nv_bfloat162*)g_lo)[base / 2 + 1] = __nv_bfloat162(l2, l3);

        float s = v.x * v.x + v.y * v.y + v.z * v.z + v.w * v.w;
        #pragma unroll
        for (int o = 16; o; o >>= 1) s += __shfl_xor_sync(0xffffffffu, s, o);
        if (lane == 0) { g_sq[i] = s; wsq += s; }
    }
    atomicAdd(&g_colsum[lane * 4 + 0], cs0);
    atomicAdd(&g_colsum[lane * 4 + 1], cs1);
    atomicAdd(&g_colsum[lane * 4 + 2], cs2);
    atomicAdd(&g_colsum[lane * 4 + 3], cs3);
    if (lane == 0) atomicAdd(&g_sumsq, wsq);
}

// ---------------- kernel 2: bandwidth ----------------
__global__ void k_bw() {
    __shared__ double sh[D];
    int t = threadIdx.x;
    double m = (double)g_colsum[t];
    sh[t] = m * m;
    __syncthreads();
    for (int o = 64; o; o >>= 1) {
        if (t < o) sh[t] += sh[t + o];
        __syncthreads();
    }
    if (t == 0) {
        double sumL2 = 2.0 * (double)NS * (double)g_sumsq - 2.0 * sh[0];
        double bw = sumL2 / ((double)NS * (double)NS - (double)NS) / 4.0;
        g_c = (float)(1.4426950408889634 / (bw * 16.0));
    }
}

// ---------------- kernel 3: HMMA Gram tile + RBF epilogue ----------------
// One block = one 128x128 tile (lower triangle). 8 warps in 4x2 grid:
// warp (wr, wc) owns rows wr*32..+31, cols wc*64..+63.
// 3-pass hi/lo bf16 split, fp32 accumulators in registers.
__global__ void __launch_bounds__(256, 2) k_main() {
    extern __shared__ char smp[];
    uint32_t smb = smem_u32(smp);

    int tid = threadIdx.x;
    int wid = tid >> 5, lane = tid & 31;
    int wr = wid & 3, wc = wid >> 2;

    // tile coords (lower triangle)
    int idx = blockIdx.x;
    int bi = (int)((sqrtf(8.0f * (float)idx + 1.0f) - 1.0f) * 0.5f);
    while ((bi + 1) * (bi + 2) / 2 <= idx) bi++;
    while (bi * (bi + 1) / 2 > idx) bi--;
    int bj = idx - bi * (bi + 1) / 2;

    const __nv_bfloat16* gm[4] = {
        g_hi + (size_t)bi * 128 * D,   // Ahi
        g_lo + (size_t)bi * 128 * D,   // Alo
        g_hi + (size_t)bj * 128 * D,   // Bhi
        g_lo + (size_t)bj * 128 * D    // Blo
    };

    // stage row norms
    float* sqi_s = (float*)(smp + SQI_OFF);
    float* sqj_s = (float*)(smp + SQJ_OFF);
    if (tid < 128)      sqi_s[tid] = g_sq[bi * 128 + tid];
    else                sqj_s[tid - 128] = g_sq[bj * 128 + (tid - 128)];

    // prefetch helper: k-chunk kc (32 elems) into buffer buf
    auto prefetch = [&](int kc, int buf) {
        #pragma unroll
        for (int m = 0; m < 4; ++m) {
            #pragma unroll
            for (int u = 0; u < 2; ++u) {
                int e = tid * 2 + u;          // 0..511
                int r = e >> 2, c2 = e & 3;   // row, 16B sub-chunk
                const void* src = gm[m] + (size_t)r * D + kc * 32 + c2 * 8;
                uint32_t dst = smb + (uint32_t)(buf * BUFSZ + m * MATSZ + r * SROW + c2 * 16);
                CP_ASYNC16(dst, src);
            }
        }
    };

    prefetch(0, 0);
    CP_COMMIT();

    float acc[2][8][4];
    #pragma unroll
    for (int a = 0; a < 2; ++a)
        #pragma unroll
        for (int b = 0; b < 8; ++b)
            #pragma unroll
            for (int q = 0; q < 4; ++q) acc[a][b][q] = 0.f;

    // ldmatrix lane addressing (constant across k)
    int arow = wr * 32 + (lane & 15);               // A rows for each m16 block (+16 for mb=1)
    int akh  = (lane >> 4) & 1;                     // A k-half
    int brow = wc * 64 + (lane & 7) + ((lane >> 4) & 1) * 8;  // B rows for each n16 group
    int bkh  = (lane >> 3) & 1;                     // B k-half

    for (int kc = 0; kc < 4; ++kc) {
        CP_WAIT0();
        __syncthreads();
        if (kc < 3) { prefetch(kc + 1, (kc + 1) & 1); CP_COMMIT(); }

        uint32_t base = smb + (uint32_t)((kc & 1) * BUFSZ);
        #pragma unroll
        for (int s = 0; s < 2; ++s) {               // two k16 steps per chunk
            uint32_t ahi[2][4], alo[2][4];
            #pragma unroll
            for (int mb = 0; mb < 2; ++mb) {
                uint32_t aaddr = base + (uint32_t)((arow + mb * 16) * SROW + (s * 2 + akh) * 16);
                ldsm4(ahi[mb], aaddr);               // Ahi at matrix offset 0
                ldsm4(alo[mb], aaddr + MATSZ);       // Alo
            }
            #pragma unroll
            for (int nbp = 0; nbp < 4; ++nbp) {      // n16 groups
                uint32_t baddr = base + (uint32_t)(2 * MATSZ +
                                   (brow + nbp * 16) * SROW + (s * 2 + bkh) * 16);
                uint32_t bhi[4], blo[4];
                ldsm4(bhi, baddr);                   // Bhi
                ldsm4(blo, baddr + MATSZ);           // Blo
                #pragma unroll
                for (int mb = 0; mb < 2; ++mb) {
                    #pragma unroll
                    for (int h = 0; h < 2; ++h) {
                        float* d = acc[mb][nbp * 2 + h];
                        mma16816(d, ahi[mb], &bhi[h * 2]);
                        mma16816(d, ahi[mb], &blo[h * 2]);
                        mma16816(d, alo[mb], &bhi[h * 2]);
                    }
                }
            }
        }
    }

    // ---- epilogue: L2 -> t = 2^(-L2*c) -> t + t^2 + t^4 + t^8 + t^16 ----
    float c = g_c;
    bool dt = (bi == bj);
    float p = 0.f;
    #pragma unroll
    for (int mb = 0; mb < 2; ++mb) {
        #pragma unroll
        for (int nb = 0; nb < 8; ++nb) {
            #pragma unroll
            for (int q = 0; q < 4; ++q) {
                int row = wr * 32 + mb * 16 + (lane >> 2) + (q >> 1) * 8;
                int col = wc * 64 + nb * 8 + (lane & 3) * 2 + (q & 1);
                float dot = acc[mb][nb][q];
                float L2 = fmaxf(sqi_s[row] + sqj_s[col] - 2.0f * dot, 0.0f);
                float t = ex2f(-L2 * c);
                float t2 = t * t, t4 = t2 * t2, t8 = t4 * t4, t16 = t8 * t8;
                float ks = t + t2 + t4 + t8 + t16;
                if (!dt || row > col) p += ks;
            }
        }
    }
    float scale = ((bi < 32) == (bj < 32)) ? 2.0f : -2.0f;
    p *= scale;

    float* red = (float*)(smp + RED_OFF);
    red[tid] = p;
    __syncthreads();
    for (int o = 128; o; o >>= 1) {
        if (tid < o) red[tid] += red[tid + o];
        __syncthreads();
    }
    if (tid == 0) atomicAdd(&g_total, (double)red[0]);
}

// ---------------- kernel 4: finalize ----------------
__global__ void k_final(float* out) {
    out[0] = (float)((g_total + 40960.0) / 16777216.0);  // diag 5*8192; / 4096^2
}

// ---------------- launcher ----------------
extern "C" void kernel_launch(void* const* d_in, const int* in_sizes, int n_in,
                              void* d_out, int out_size) {
    const float* src = (const float*)d_in[0];
    const float* tgt = (const float*)d_in[1];
    float* out = (float*)d_out;
    (void)in_sizes; (void)n_in; (void)out_size;

    cudaFuncSetAttribute(k_main, cudaFuncAttributeMaxDynamicSharedMemorySize, SMEM_BYTES);

    k_init<<<1, 256>>>();
    k_rowstats<<<64, 256>>>(src, tgt);
    k_bw<<<1, D>>>();
    k_main<<<NBLOCKS, 256, SMEM_BYTES>>>();
    k_final<<<1, 1>>>(out);
}